// round 14
// baseline (speedup 1.0000x reference)
#include <cuda_runtime.h>
#include <cstdint>

// Problem shape (fixed by the dataset).
#define BDIM   8
#define NROWS  2048
#define LCOLS  2048
#define QROWS  512
#define DDIM   512
#define NHEAD  4

// K1 tiling: 128 l per block, 8 q-segments of 64 rows, thread owns 4 l's.
#define SEG    8
#define SROWS  (QROWS / SEG)   // 64

// Scratch: per (b, l, head) one float4 = {w0, w1, w2, bitcast(i0|i1<<10|i2<<20)}.
__device__ float4 g_tw[(size_t)BDIM * LCOLS * NHEAD];

// ---------------------------------------------------------------------------
// Kernel 1: top-3 + softmax.
//  - float4 over l: each thread owns 4 consecutive l's -> 512B/warp per LDG.
//  - rare-branch insert: common path is ONE compare (v > t2), full cascade
//    only on the ~15/64 expected insertions.
//  - 8-way q-split; merge over segments done by 128 threads (one per l).
// ---------------------------------------------------------------------------
__global__ __launch_bounds__(256) void topk_softmax_kernel(
    const float* __restrict__ logits)
{
    const int x     = threadIdx.x;          // 0..31, covers 4 l's each
    const int s     = threadIdx.y;          // 0..7 q-segment
    const int lbase = blockIdx.x * 128;
    const int h     = blockIdx.y;
    const int b     = blockIdx.z;

    const float4* p = (const float4*)(logits
        + ((size_t)b * NROWS + (size_t)h * QROWS + (size_t)s * SROWS) * LCOLS
        + lbase) + x;

    float t0[4], t1[4], t2[4];
    int   i0[4], i1[4], i2[4];
#pragma unroll
    for (int il = 0; il < 4; ++il) {
        t0[il] = t1[il] = t2[il] = -3.4e38f;
        i0[il] = i1[il] = i2[il] = 0;
    }

#pragma unroll 8
    for (int j = 0; j < SROWS; ++j) {
        float4 v4 = __ldg(p + (size_t)j * (LCOLS / 4));
        float v[4] = { v4.x, v4.y, v4.z, v4.w };
#pragma unroll
        for (int il = 0; il < 4; ++il) {
            float vv = v[il];
            if (vv > t2[il]) {                       // rare (≈ 15 of 64)
                if (vv > t0[il]) {
                    t2[il] = t1[il]; i2[il] = i1[il];
                    t1[il] = t0[il]; i1[il] = i0[il];
                    t0[il] = vv;     i0[il] = j;
                } else if (vv > t1[il]) {
                    t2[il] = t1[il]; i2[il] = i1[il];
                    t1[il] = vv;     i1[il] = j;
                } else {
                    t2[il] = vv;     i2[il] = j;
                }
            }
        }
    }

    // Per (segment, l): {t0,t1,t2, packed global indices (9b each)}.
    __shared__ float4 sm[SEG][128];
#pragma unroll
    for (int il = 0; il < 4; ++il) {
        unsigned pk = (unsigned)(i0[il] + s * SROWS)
                    | ((unsigned)(i1[il] + s * SROWS) << 9)
                    | ((unsigned)(i2[il] + s * SROWS) << 18);
        sm[s][x * 4 + il] = make_float4(t0[il], t1[il], t2[il],
                                        __uint_as_float(pk));
    }
    __syncthreads();

    // Merge: 128 threads (s<4), thread handles l = x*4 + s.
    if (s < 4) {
        const int lr = x * 4 + s;

        float m0 = -3.4e38f, m1 = -3.4e38f, m2 = -3.4e38f;
        int   j0 = 0, j1 = 0, j2 = 0;
        // Segments ascending; within segment candidates are descending-value
        // with ascending index among equals. Strict '>' preserves top_k's
        // first-index-wins tie rule.
#pragma unroll
        for (int ss = 0; ss < SEG; ++ss) {
            float4 c = sm[ss][lr];
            unsigned pk = __float_as_uint(c.w);
            float cv[3] = { c.x, c.y, c.z };
            int   ci[3] = { (int)( pk        & 511),
                            (int)((pk >> 9)  & 511),
                            (int)((pk >> 18) & 511) };
#pragma unroll
            for (int k = 0; k < 3; ++k) {
                float v = cv[k]; int idx = ci[k];
                if (v > m2) {
                    if (v > m0)      { m2 = m1; j2 = j1; m1 = m0; j1 = j0;
                                       m0 = v;  j0 = idx; }
                    else if (v > m1) { m2 = m1; j2 = j1; m1 = v; j1 = idx; }
                    else             { m2 = v;  j2 = idx; }
                }
            }
        }

        float e1  = __expf(m1 - m0);
        float e2  = __expf(m2 - m0);
        float inv = 1.0f / (1.0f + e1 + e2);

        float4 r;
        r.x = inv;
        r.y = e1 * inv;
        r.z = e2 * inv;
        r.w = __uint_as_float((unsigned)j0 | ((unsigned)j1 << 10)
                              | ((unsigned)j2 << 20));
        g_tw[((size_t)b * LCOLS + (lbase + lr)) * NHEAD + h] = r;
    }
}

// ---------------------------------------------------------------------------
// Kernel 2: combine (unchanged from R13 — 26.6us, L1/L2 balanced).
// ---------------------------------------------------------------------------
#define K2_WARPS 8
#define K2_WL    2
#define K2_LT    (K2_WARPS * K2_WL)
#define K2_PAD   516

__global__ __launch_bounds__(256) void combine_kernel(
    const float* __restrict__ e0, const float* __restrict__ e1,
    const float* __restrict__ e2, const float* __restrict__ e3,
    float* __restrict__ out)
{
    const int tid   = threadIdx.x;
    const int warp  = tid >> 5;
    const int lane  = tid & 31;
    const int lbase = blockIdx.x * K2_LT;
    const int b     = blockIdx.y;

    const float* embs[NHEAD] = { e0, e1, e2, e3 };

    __shared__ float sm[K2_LT][K2_PAD];

    float4 acc[K2_WL][4];
#pragma unroll
    for (int il = 0; il < K2_WL; ++il)
#pragma unroll
        for (int c = 0; c < 4; ++c)
            acc[il][c] = make_float4(0.f, 0.f, 0.f, 0.f);

#pragma unroll
    for (int il = 0; il < K2_WL; ++il) {
        const int l = lbase + warp * K2_WL + il;
#pragma unroll
        for (int h = 0; h < NHEAD; ++h) {
            float4 tw = g_tw[((size_t)b * LCOLS + l) * NHEAD + h];
            unsigned pk = __float_as_uint(tw.w);
            float w[3]   = { tw.x, tw.y, tw.z };
            int   idx[3] = { (int)( pk        & 0x3FF),
                             (int)((pk >> 10) & 0x3FF),
                             (int)((pk >> 20) & 0x3FF) };
#pragma unroll
            for (int k = 0; k < 3; ++k) {
                const float4* row =
                    (const float4*)(embs[h] + (size_t)idx[k] * DDIM) + lane;
                const float wk = w[k];
#pragma unroll
                for (int c = 0; c < 4; ++c) {
                    float4 v = __ldg(row + c * 32);
                    acc[il][c].x = fmaf(wk, v.x, acc[il][c].x);
                    acc[il][c].y = fmaf(wk, v.y, acc[il][c].y);
                    acc[il][c].z = fmaf(wk, v.z, acc[il][c].z);
                    acc[il][c].w = fmaf(wk, v.w, acc[il][c].w);
                }
            }
        }
    }

#pragma unroll
    for (int il = 0; il < K2_WL; ++il) {
        const int lrow = warp * K2_WL + il;
#pragma unroll
        for (int c = 0; c < 4; ++c)
            *(float4*)&sm[lrow][c * 128 + lane * 4] = acc[il][c];
    }
    __syncthreads();

    float* obase = out + (size_t)b * DDIM * LCOLS + lbase;
#pragma unroll
    for (int r = 0; r < (DDIM * K2_LT) / 256; ++r) {
        int linear = r * 256 + tid;
        int d = linear >> 4;
        int l = linear & 15;
        obase[(size_t)d * LCOLS + l] = sm[l][d];
    }
}

// ---------------------------------------------------------------------------
extern "C" void kernel_launch(void* const* d_in, const int* in_sizes, int n_in,
                              void* d_out, int out_size)
{
    const float* logits = (const float*)d_in[0];
    const float* e0     = (const float*)d_in[1];
    const float* e1     = (const float*)d_in[2];
    const float* e2     = (const float*)d_in[3];
    const float* e3     = (const float*)d_in[4];
    float*       out    = (float*)d_out;

    dim3 g1(LCOLS / 128, NHEAD, BDIM);     // (16, 4, 8) = 512 blocks
    dim3 b1(32, SEG, 1);                   // 256 threads
    topk_softmax_kernel<<<g1, b1>>>(logits);

    dim3 g2(LCOLS / K2_LT, BDIM, 1);       // (128, 8) = 1024 blocks
    combine_kernel<<<g2, 256>>>(e0, e1, e2, e3, out);
}